// round 2
// baseline (speedup 1.0000x reference)
#include <cuda_runtime.h>
#include <cstdint>

#define N_NODES 50000
#define N_EDGES 500000
#define IN_CH   128
#define QKVC    256        // OUT_CH * HEADS
#define OUTC    64
#define HEADS   4
#define N_PAD   50048      // 391*128 = 782*64
#define LOGIT_BLOCKS (N_EDGES / 8)   // 62500, exact

// ---------------- scratch (device globals; no allocation allowed) ----------
__device__ float g_Q[(size_t)N_PAD * QKVC];
__device__ float g_K[(size_t)N_PAD * QKVC];
__device__ float g_V[(size_t)N_PAD * QKVC];
__device__ float g_agg[(size_t)N_PAD * QKVC];
__device__ float g_logit[(size_t)N_EDGES * HEADS];   // logits, then exp() in-place
__device__ float g_blockmax[LOGIT_BLOCKS * HEADS];
__device__ float g_max[HEADS];
__device__ float g_sum[HEADS];
__device__ int   g_idx64;

// ---------------- helpers --------------------------------------------------
__device__ __forceinline__ void red_add_v4(float* p, float a, float b, float c, float d) {
    asm volatile("red.global.add.v4.f32 [%0], {%1,%2,%3,%4};"
                 :: "l"(p), "f"(a), "f"(b), "f"(c), "f"(d) : "memory");
}

__device__ __forceinline__ void load_edge(const void* ei_raw, int e, int idx64,
                                          int& s, int& t) {
    if (idx64) {
        const long long* p = (const long long*)ei_raw;
        s = (int)p[e];
        t = (int)p[N_EDGES + e];
    } else {
        const int* p = (const int*)ei_raw;
        s = p[e];
        t = p[N_EDGES + e];
    }
}

// ---------------- 0: dtype sniff + zero scratch ----------------------------
__global__ void detect_idx_kernel(const int* ei32) {
    if (blockIdx.x == 0 && threadIdx.x == 0) {
        int zeros = 0;
        for (int i = 0; i < 64; i++)
            if (ei32[2 * i + 1] == 0) zeros++;
        g_idx64 = (zeros >= 60) ? 1 : 0;   // int64 ids < 2^31 -> high words all 0
    }
}

__global__ void zero_kernel() {
    size_t i = ((size_t)blockIdx.x * 256 + threadIdx.x) * 4;
    if (i < (size_t)N_PAD * QKVC) {
        float4 z = make_float4(0.f, 0.f, 0.f, 0.f);
        *(float4*)&g_agg[i] = z;
    }
    if (blockIdx.x == 0 && threadIdx.x < HEADS) g_sum[threadIdx.x] = 0.f;
}

// ---------------- 1: QKV projection, 128x128x8 fp32 GEMM -------------------
// C[z] = x @ W[z],  x:[M,128], W:[128,256].  grid = (391, 2, 3)
__global__ void __launch_bounds__(256) qkv_gemm_kernel(
    const float* __restrict__ A,
    const float* __restrict__ Wq, const float* __restrict__ Wk,
    const float* __restrict__ Wv)
{
    const int BM = 128, BN = 128, BK = 8;
    const int M = N_NODES, K = IN_CH, NB = QKVC;
    __shared__ float As[BK][BM];
    __shared__ float Bs[BK][BN];

    const float* B = (blockIdx.z == 0) ? Wq : (blockIdx.z == 1) ? Wk : Wv;
    float* C = (blockIdx.z == 0) ? g_Q : (blockIdx.z == 1) ? g_K : g_V;

    int tid = threadIdx.x;
    int row0 = blockIdx.x * BM;
    int col0 = blockIdx.y * BN;
    int tx = tid & 15, ty = tid >> 4;

    int arow = tid >> 1;            // 0..127
    int acol = (tid & 1) * 4;       // 0 or 4
    int brow = tid >> 5;            // 0..7
    int bcol = (tid & 31) * 4;      // 0..124

    float acc[8][8];
#pragma unroll
    for (int i = 0; i < 8; i++)
#pragma unroll
        for (int j = 0; j < 8; j++) acc[i][j] = 0.f;

    for (int k0 = 0; k0 < K; k0 += BK) {
        float4 av = make_float4(0.f, 0.f, 0.f, 0.f);
        int gr = row0 + arow;
        if (gr < M) av = *(const float4*)&A[(size_t)gr * K + k0 + acol];
        As[acol + 0][arow] = av.x;
        As[acol + 1][arow] = av.y;
        As[acol + 2][arow] = av.z;
        As[acol + 3][arow] = av.w;

        float4 bv = *(const float4*)&B[(size_t)(k0 + brow) * NB + col0 + bcol];
        *(float4*)&Bs[brow][bcol] = bv;
        __syncthreads();

#pragma unroll
        for (int k = 0; k < BK; k++) {
            float4 a0 = *(float4*)&As[k][ty * 8];
            float4 a1 = *(float4*)&As[k][ty * 8 + 4];
            float4 b0 = *(float4*)&Bs[k][tx * 8];
            float4 b1 = *(float4*)&Bs[k][tx * 8 + 4];
            float ar[8] = {a0.x, a0.y, a0.z, a0.w, a1.x, a1.y, a1.z, a1.w};
            float br[8] = {b0.x, b0.y, b0.z, b0.w, b1.x, b1.y, b1.z, b1.w};
#pragma unroll
            for (int i = 0; i < 8; i++)
#pragma unroll
                for (int j = 0; j < 8; j++) acc[i][j] += ar[i] * br[j];
        }
        __syncthreads();
    }

#pragma unroll
    for (int i = 0; i < 8; i++) {
        int r = row0 + ty * 8 + i;
        if (r >= M) continue;
#pragma unroll
        for (int j = 0; j < 8; j += 4) {
            float4 v = make_float4(acc[i][j], acc[i][j + 1], acc[i][j + 2], acc[i][j + 3]);
            *(float4*)&C[(size_t)r * NB + col0 + tx * 8 + j] = v;
        }
    }
}

// ---------------- 2: per-edge attention logits (warp per edge) -------------
__global__ void __launch_bounds__(256) edge_logits_kernel(
    const void* __restrict__ ei_raw,
    const float* __restrict__ ew,
    const float* __restrict__ We)
{
    __shared__ float wvals[8][HEADS];
    int wid = threadIdx.x >> 5;
    int lane = threadIdx.x & 31;
    int e = blockIdx.x * 8 + wid;
    int idx64 = g_idx64;

    int s, t;
    load_edge(ei_raw, e, idx64, s, t);

    const float4* q = (const float4*)(g_Q + (size_t)t * QKVC);
    const float4* k = (const float4*)(g_K + (size_t)s * QKVC);
    float4 q0 = q[lane * 2], q1 = q[lane * 2 + 1];
    float4 k0 = k[lane * 2], k1 = k[lane * 2 + 1];

    float ps = q0.x * k0.x + q0.y * k0.y + q0.z * k0.z + q0.w * k0.w
             + q1.x * k1.x + q1.y * k1.y + q1.z * k1.z + q1.w * k1.w;
    // each lane covers 8 consecutive channels; head = lane>>3; reduce 8-lane groups
    ps += __shfl_xor_sync(0xffffffffu, ps, 4);
    ps += __shfl_xor_sync(0xffffffffu, ps, 2);
    ps += __shfl_xor_sync(0xffffffffu, ps, 1);

    if ((lane & 7) == 0) {
        int h = lane >> 3;
        float logit = ps * 0.125f + ew[e] * We[h];      // 1/sqrt(64) = 0.125
        logit = (logit > 0.f) ? logit : 0.2f * logit;   // leaky relu
        g_logit[(size_t)e * HEADS + h] = logit;
        wvals[wid][h] = logit;
    }
    __syncthreads();
    if (threadIdx.x < HEADS) {
        float m = wvals[0][threadIdx.x];
#pragma unroll
        for (int w = 1; w < 8; w++) m = fmaxf(m, wvals[w][threadIdx.x]);
        g_blockmax[blockIdx.x * HEADS + threadIdx.x] = m;
    }
}

// ---------------- 3: global max per head -----------------------------------
__global__ void reduce_max_kernel() {
    int h = blockIdx.x;
    __shared__ float sm[256];
    float m = -3.4e38f;
    for (int i = threadIdx.x; i < LOGIT_BLOCKS; i += 256)
        m = fmaxf(m, g_blockmax[i * HEADS + h]);
    sm[threadIdx.x] = m;
    __syncthreads();
    for (int s = 128; s > 0; s >>= 1) {
        if (threadIdx.x < s) sm[threadIdx.x] = fmaxf(sm[threadIdx.x], sm[threadIdx.x + s]);
        __syncthreads();
    }
    if (threadIdx.x == 0) g_max[h] = sm[0];
}

// ---------------- 4: exp (in place) + per-head sum -------------------------
__global__ void __launch_bounds__(256) coef_kernel() {
    __shared__ float ssum[HEADS];
    if (threadIdx.x < HEADS) ssum[threadIdx.x] = 0.f;
    __syncthreads();

    int e = blockIdx.x * 256 + threadIdx.x;
    float c0 = 0.f, c1 = 0.f, c2 = 0.f, c3 = 0.f;
    if (e < N_EDGES) {
        float4 l = *(float4*)&g_logit[(size_t)e * HEADS];
        c0 = __expf(l.x - g_max[0]);
        c1 = __expf(l.y - g_max[1]);
        c2 = __expf(l.z - g_max[2]);
        c3 = __expf(l.w - g_max[3]);
        float4 v = make_float4(c0, c1, c2, c3);
        *(float4*)&g_logit[(size_t)e * HEADS] = v;
    }
#pragma unroll
    for (int m = 16; m > 0; m >>= 1) {
        c0 += __shfl_xor_sync(0xffffffffu, c0, m);
        c1 += __shfl_xor_sync(0xffffffffu, c1, m);
        c2 += __shfl_xor_sync(0xffffffffu, c2, m);
        c3 += __shfl_xor_sync(0xffffffffu, c3, m);
    }
    if ((threadIdx.x & 31) == 0) {
        atomicAdd(&ssum[0], c0);
        atomicAdd(&ssum[1], c1);
        atomicAdd(&ssum[2], c2);
        atomicAdd(&ssum[3], c3);
    }
    __syncthreads();
    if (threadIdx.x < HEADS) atomicAdd(&g_sum[threadIdx.x], ssum[threadIdx.x]);
}

// ---------------- 5: weighted scatter-aggregate (warp per edge) ------------
__global__ void __launch_bounds__(256) agg_kernel(const void* __restrict__ ei_raw) {
    int wid = threadIdx.x >> 5;
    int lane = threadIdx.x & 31;
    int e = blockIdx.x * 8 + wid;
    int idx64 = g_idx64;

    int s, t;
    load_edge(ei_raw, e, idx64, s, t);

    int h = lane >> 3;
    float coef = g_logit[(size_t)e * HEADS + h] * (1.0f / g_sum[h]);

    const float4* v = (const float4*)(g_V + (size_t)s * QKVC);
    float4 v0 = v[lane * 2], v1 = v[lane * 2 + 1];

    float* dst = g_agg + (size_t)t * QKVC + lane * 8;
    red_add_v4(dst,     coef * v0.x, coef * v0.y, coef * v0.z, coef * v0.w);
    red_add_v4(dst + 4, coef * v1.x, coef * v1.y, coef * v1.z, coef * v1.w);
}

// ---------------- 6: output GEMM (+bias), 64x64x16 -------------------------
// out = g_agg[N,256] @ Wout[256,64] + b
__global__ void __launch_bounds__(256) out_gemm_kernel(
    const float* __restrict__ B, const float* __restrict__ bias,
    float* __restrict__ C)
{
    const int BM = 64, BK = 16;
    const int M = N_NODES, K = QKVC, NB = OUTC;
    __shared__ float As[BM][BK + 1];
    __shared__ float Bs[BK][68];

    int tid = threadIdx.x;
    int row0 = blockIdx.x * BM;
    int tx = tid & 15, ty = tid >> 4;

    float acc[4][4];
#pragma unroll
    for (int i = 0; i < 4; i++)
#pragma unroll
        for (int j = 0; j < 4; j++) acc[i][j] = 0.f;

    for (int k0 = 0; k0 < K; k0 += BK) {
        {
            int r = tid >> 2;             // 0..63
            int c4 = (tid & 3) * 4;       // 0..12
            int gr = row0 + r;
            float4 v = make_float4(0.f, 0.f, 0.f, 0.f);
            if (gr < M) v = *(const float4*)&g_agg[(size_t)gr * K + k0 + c4];
            As[r][c4 + 0] = v.x; As[r][c4 + 1] = v.y;
            As[r][c4 + 2] = v.z; As[r][c4 + 3] = v.w;
        }
        {
            int r = tid >> 4;             // 0..15
            int c4 = (tid & 15) * 4;      // 0..60
            float4 v = *(const float4*)&B[(size_t)(k0 + r) * NB + c4];
            Bs[r][c4 + 0] = v.x; Bs[r][c4 + 1] = v.y;
            Bs[r][c4 + 2] = v.z; Bs[r][c4 + 3] = v.w;
        }
        __syncthreads();
#pragma unroll
        for (int k = 0; k < BK; k++) {
            float ar[4], br[4];
#pragma unroll
            for (int i = 0; i < 4; i++) ar[i] = As[ty * 4 + i][k];
#pragma unroll
            for (int j = 0; j < 4; j++) br[j] = Bs[k][tx * 4 + j];
#pragma unroll
            for (int i = 0; i < 4; i++)
#pragma unroll
                for (int j = 0; j < 4; j++) acc[i][j] += ar[i] * br[j];
        }
        __syncthreads();
    }

#pragma unroll
    for (int i = 0; i < 4; i++) {
        int r = row0 + ty * 4 + i;
        if (r >= M) continue;
#pragma unroll
        for (int j = 0; j < 4; j++) {
            int c = tx * 4 + j;
            C[(size_t)r * NB + c] = acc[i][j] + bias[c];
        }
    }
}

// ---------------- launch ----------------------------------------------------
extern "C" void kernel_launch(void* const* d_in, const int* in_sizes, int n_in,
                              void* d_out, int out_size) {
    const float* x    = (const float*)d_in[0];
    const void*  ei   = d_in[1];                 // int64 or int32, sniffed
    const float* ew   = (const float*)d_in[2];
    const float* Wq   = (const float*)d_in[3];
    const float* Wk   = (const float*)d_in[4];
    const float* Wv   = (const float*)d_in[5];
    const float* We   = (const float*)d_in[6];
    const float* Wout = (const float*)d_in[7];
    const float* bout = (const float*)d_in[8];
    float* out = (float*)d_out;

    detect_idx_kernel<<<1, 32>>>((const int*)ei);

    // zero agg + sums
    int zb = (int)(((size_t)N_PAD * QKVC) / 1024);   // 12512
    zero_kernel<<<zb, 256>>>();

    // Q,K,V = x @ W*
    dim3 ggrid(N_PAD / 128, QKVC / 128, 3);
    qkv_gemm_kernel<<<ggrid, 256>>>(x, Wq, Wk, Wv);

    // logits + per-block max
    edge_logits_kernel<<<LOGIT_BLOCKS, 256>>>(ei, ew, We);

    // global max per head
    reduce_max_kernel<<<HEADS, 256>>>();

    // exp + sums
    coef_kernel<<<(N_EDGES + 255) / 256, 256>>>();

    // weighted scatter aggregation
    agg_kernel<<<LOGIT_BLOCKS, 256>>>(ei);

    // out = agg @ Wout + b
    out_gemm_kernel<<<N_PAD / 64, 256>>>(Wout, bout, out);
}

// round 7
// speedup vs baseline: 1.2022x; 1.2022x over previous
#include <cuda_runtime.h>
#include <cuda_bf16.h>
#include <mma.h>
#include <cstdint>

using namespace nvcuda;

#define N_NODES 50000
#define N_EDGES 500000
#define IN_CH   128
#define QKVC    256        // OUT_CH * HEADS
#define OUTC    64
#define HEADS   4
#define N_PAD   50048      // 391*128 = 782*64
#define LOGIT_BLOCKS (N_EDGES / 8)   // 62500, exact
#define M_TILES (N_PAD / 128)        // 391

// ---------------- scratch (device globals; no allocation allowed) ----------
__device__ float g_Q[(size_t)N_PAD * QKVC];
__device__ float g_K[(size_t)N_PAD * QKVC];
__device__ float g_V[(size_t)N_PAD * QKVC];
__device__ float g_agg[(size_t)N_PAD * QKVC];
__device__ float g_logit[(size_t)N_EDGES * HEADS];
__device__ float g_blockmax[LOGIT_BLOCKS * HEADS];
__device__ float g_max[HEADS];
__device__ float g_sum[HEADS];
__device__ int   g_idx64;

// split-bf16 operands for the HMMA path
__device__ __align__(16) uint4 g_xhi[(size_t)N_PAD * 16];   // [N_PAD][128] bf16 rows, 8 per uint4
__device__ __align__(16) uint4 g_xlo[(size_t)N_PAD * 16];
__device__ __align__(16) uint4 g_Wt[3 * 2 * 256 * 16];      // [w][hi/lo][n=256][k=128] bf16 (W^T)

// ---------------- helpers --------------------------------------------------
__device__ __forceinline__ void red_add_v4(float* p, float a, float b, float c, float d) {
    asm volatile("red.global.add.v4.f32 [%0], {%1,%2,%3,%4};"
                 :: "l"(p), "f"(a), "f"(b), "f"(c), "f"(d) : "memory");
}
__device__ __forceinline__ void load_edge(const void* ei_raw, int e, int idx64,
                                          int& s, int& t) {
    if (idx64) {
        const long long* p = (const long long*)ei_raw;
        s = (int)p[e];
        t = (int)p[N_EDGES + e];
    } else {
        const int* p = (const int*)ei_raw;
        s = p[e];
        t = p[N_EDGES + e];
    }
}

// ---------------- 0: dtype sniff + zero scratch ----------------------------
__global__ void detect_idx_kernel(const int* ei32) {
    if (blockIdx.x == 0 && threadIdx.x == 0) {
        int zeros = 0;
        for (int i = 0; i < 64; i++)
            if (ei32[2 * i + 1] == 0) zeros++;
        g_idx64 = (zeros >= 60) ? 1 : 0;
    }
}
__global__ void zero_kernel() {
    size_t i = ((size_t)blockIdx.x * 256 + threadIdx.x) * 4;
    if (i < (size_t)N_PAD * QKVC)
        *(float4*)&g_agg[i] = make_float4(0.f, 0.f, 0.f, 0.f);
    if (blockIdx.x == 0 && threadIdx.x < HEADS) g_sum[threadIdx.x] = 0.f;
}

// ---------------- 1a: split x -> bf16 hi/lo ---------------------------------
__global__ void __launch_bounds__(256) prep_x_kernel(const float* __restrict__ x) {
    int t = blockIdx.x * 256 + threadIdx.x;       // one per 8-float chunk
    if (t >= N_PAD * 16) return;
    int r = t >> 4, c8 = t & 15;
    float v[8];
    if (r < N_NODES) {
        float4 a = *(const float4*)&x[(size_t)r * IN_CH + c8 * 8];
        float4 b = *(const float4*)&x[(size_t)r * IN_CH + c8 * 8 + 4];
        v[0] = a.x; v[1] = a.y; v[2] = a.z; v[3] = a.w;
        v[4] = b.x; v[5] = b.y; v[6] = b.z; v[7] = b.w;
    } else {
#pragma unroll
        for (int j = 0; j < 8; j++) v[j] = 0.f;
    }
    union { __nv_bfloat16 h[8]; uint4 u; } hi, lo;
#pragma unroll
    for (int j = 0; j < 8; j++) {
        __nv_bfloat16 h = __float2bfloat16_rn(v[j]);
        hi.h[j] = h;
        lo.h[j] = __float2bfloat16_rn(v[j] - __bfloat162float(h));
    }
    g_xhi[t] = hi.u;
    g_xlo[t] = lo.u;
}

// ---------------- 1b: W^T hi/lo images ([n][k] row-major bf16) --------------
__global__ void __launch_bounds__(256) prep_w_kernel(
    const float* __restrict__ Wq, const float* __restrict__ Wk,
    const float* __restrict__ Wv) {
    int t = blockIdx.x * 256 + threadIdx.x;       // 3*256*16 = 12288 (w, n, k8)
    if (t >= 3 * 256 * 16) return;
    int w = t >> 12;
    int n = (t >> 4) & 255;
    int k8 = t & 15;
    const float* W = (w == 0) ? Wq : (w == 1) ? Wk : Wv;
    union { __nv_bfloat16 h[8]; uint4 u; } hi, lo;
#pragma unroll
    for (int j = 0; j < 8; j++) {
        float v = W[(size_t)(k8 * 8 + j) * QKVC + n];
        __nv_bfloat16 h = __float2bfloat16_rn(v);
        hi.h[j] = h;
        lo.h[j] = __float2bfloat16_rn(v - __bfloat162float(h));
    }
    g_Wt[((w * 2 + 0) * 256 + n) * 16 + k8] = hi.u;
    g_Wt[((w * 2 + 1) * 256 + n) * 16 + k8] = lo.u;
}

// ---------------- 1c: QKV GEMM via wmma bf16 (3-term split, fp32 acc) -------
// grid (391, 2): CTA outputs rows [bx*128,+128) x cols [by*128,+128) for all
// three weights (z-loop), A tiles staged in SMEM once.
#define LDA 136                                    // padded ld (elements)
static constexpr int SA_HI = 0;
static constexpr int SA_LO = 128 * LDA * 2;        // 34816
static constexpr int SB_HI = SA_LO + 128 * LDA * 2;
static constexpr int SB_LO = SB_HI + 128 * LDA * 2;
static constexpr int SM_QKV = SB_LO + 128 * LDA * 2;  // 139264 bytes

__global__ void __launch_bounds__(256) qkv_wmma_kernel() {
    extern __shared__ __align__(16) char smem[];
    __nv_bfloat16* Ahi = (__nv_bfloat16*)(smem + SA_HI);
    __nv_bfloat16* Alo = (__nv_bfloat16*)(smem + SA_LO);
    __nv_bfloat16* Bhi = (__nv_bfloat16*)(smem + SB_HI);
    __nv_bfloat16* Blo = (__nv_bfloat16*)(smem + SB_LO);

    int tid = threadIdx.x;
    int bx = blockIdx.x, by = blockIdx.y;
    int wid = tid >> 5;
    int wr = wid & 3;           // warp row (4 x 32 rows)
    int wc = wid >> 2;          // warp col (2 x 64 cols)

    // stage A hi/lo (128 rows x 128 k)
    for (int i = tid; i < 2048; i += 256) {
        int r = i >> 4, c8 = i & 15;
        size_t src = (size_t)(bx * 128 + r) * 16 + c8;
        *(uint4*)&Ahi[r * LDA + c8 * 8] = g_xhi[src];
        *(uint4*)&Alo[r * LDA + c8 * 8] = g_xlo[src];
    }

    for (int z = 0; z < 3; z++) {
        // stage B hi/lo: rows n_local in [0,128) of W^T for cols by*128+n_local
        for (int i = tid; i < 2048; i += 256) {
            int nl = i >> 4, k8 = i & 15;
            int n = by * 128 + nl;
            *(uint4*)&Bhi[nl * LDA + k8 * 8] = g_Wt[((z * 2 + 0) * 256 + n) * 16 + k8];
            *(uint4*)&Blo[nl * LDA + k8 * 8] = g_Wt[((z * 2 + 1) * 256 + n) * 16 + k8];
        }
        __syncthreads();

        wmma::fragment<wmma::accumulator, 16, 16, 16, float> acc[2][4];
#pragma unroll
        for (int i = 0; i < 2; i++)
#pragma unroll
            for (int j = 0; j < 4; j++) wmma::fill_fragment(acc[i][j], 0.f);

#pragma unroll
        for (int term = 0; term < 3; term++) {
            const __nv_bfloat16* Ap = (term == 2) ? Alo : Ahi;
            const __nv_bfloat16* Bp = (term == 1) ? Blo : Bhi;
#pragma unroll
            for (int k0 = 0; k0 < 128; k0 += 16) {
                wmma::fragment<wmma::matrix_a, 16, 16, 16, __nv_bfloat16, wmma::row_major> a[2];
                wmma::load_matrix_sync(a[0], Ap + (wr * 32 + 0)  * LDA + k0, LDA);
                wmma::load_matrix_sync(a[1], Ap + (wr * 32 + 16) * LDA + k0, LDA);
#pragma unroll
                for (int j = 0; j < 4; j++) {
                    wmma::fragment<wmma::matrix_b, 16, 16, 16, __nv_bfloat16, wmma::col_major> b;
                    // col_major: B(k,n) = ptr[k + n*ld]; our W^T rows are n with k contiguous
                    wmma::load_matrix_sync(b, Bp + (wc * 64 + j * 16) * LDA + k0, LDA);
                    wmma::mma_sync(acc[0][j], a[0], b, acc[0][j]);
                    wmma::mma_sync(acc[1][j], a[1], b, acc[1][j]);
                }
            }
        }

        float* C = (z == 0) ? g_Q : (z == 1) ? g_K : g_V;
        int row0 = bx * 128 + wr * 32;
        int col0 = by * 128 + wc * 64;
#pragma unroll
        for (int i = 0; i < 2; i++)
#pragma unroll
            for (int j = 0; j < 4; j++)
                wmma::store_matrix_sync(&C[(size_t)(row0 + i * 16) * QKVC + col0 + j * 16],
                                        acc[i][j], QKVC, wmma::mem_row_major);
        __syncthreads();   // protect B tiles before next z overwrites them
    }
}

// ---------------- 2: per-edge attention logits (warp per edge) -------------
__global__ void __launch_bounds__(256) edge_logits_kernel(
    const void* __restrict__ ei_raw,
    const float* __restrict__ ew,
    const float* __restrict__ We)
{
    __shared__ float wvals[8][HEADS];
    int wid = threadIdx.x >> 5;
    int lane = threadIdx.x & 31;
    int e = blockIdx.x * 8 + wid;
    int idx64 = g_idx64;

    int s, t;
    load_edge(ei_raw, e, idx64, s, t);

    const float4* q = (const float4*)(g_Q + (size_t)t * QKVC);
    const float4* k = (const float4*)(g_K + (size_t)s * QKVC);
    float4 q0 = q[lane * 2], q1 = q[lane * 2 + 1];
    float4 k0 = k[lane * 2], k1 = k[lane * 2 + 1];

    float ps = q0.x * k0.x + q0.y * k0.y + q0.z * k0.z + q0.w * k0.w
             + q1.x * k1.x + q1.y * k1.y + q1.z * k1.z + q1.w * k1.w;
    ps += __shfl_xor_sync(0xffffffffu, ps, 4);
    ps += __shfl_xor_sync(0xffffffffu, ps, 2);
    ps += __shfl_xor_sync(0xffffffffu, ps, 1);

    if ((lane & 7) == 0) {
        int h = lane >> 3;
        float logit = ps * 0.125f + ew[e] * We[h];
        logit = (logit > 0.f) ? logit : 0.2f * logit;
        g_logit[(size_t)e * HEADS + h] = logit;
        wvals[wid][h] = logit;
    }
    __syncthreads();
    if (threadIdx.x < HEADS) {
        float m = wvals[0][threadIdx.x];
#pragma unroll
        for (int w = 1; w < 8; w++) m = fmaxf(m, wvals[w][threadIdx.x]);
        g_blockmax[blockIdx.x * HEADS + threadIdx.x] = m;
    }
}

// ---------------- 3: global max per head -----------------------------------
__global__ void reduce_max_kernel() {
    int h = blockIdx.x;
    __shared__ float sm[256];
    float m = -3.4e38f;
    for (int i = threadIdx.x; i < LOGIT_BLOCKS; i += 256)
        m = fmaxf(m, g_blockmax[i * HEADS + h]);
    sm[threadIdx.x] = m;
    __syncthreads();
    for (int s = 128; s > 0; s >>= 1) {
        if (threadIdx.x < s) sm[threadIdx.x] = fmaxf(sm[threadIdx.x], sm[threadIdx.x + s]);
        __syncthreads();
    }
    if (threadIdx.x == 0) g_max[h] = sm[0];
}

// ---------------- 4: exp (in place) + per-head sum -------------------------
__global__ void __launch_bounds__(256) coef_kernel() {
    __shared__ float ssum[HEADS];
    if (threadIdx.x < HEADS) ssum[threadIdx.x] = 0.f;
    __syncthreads();

    int e = blockIdx.x * 256 + threadIdx.x;
    float c0 = 0.f, c1 = 0.f, c2 = 0.f, c3 = 0.f;
    if (e < N_EDGES) {
        float4 l = *(float4*)&g_logit[(size_t)e * HEADS];
        c0 = __expf(l.x - g_max[0]);
        c1 = __expf(l.y - g_max[1]);
        c2 = __expf(l.z - g_max[2]);
        c3 = __expf(l.w - g_max[3]);
        *(float4*)&g_logit[(size_t)e * HEADS] = make_float4(c0, c1, c2, c3);
    }
#pragma unroll
    for (int m = 16; m > 0; m >>= 1) {
        c0 += __shfl_xor_sync(0xffffffffu, c0, m);
        c1 += __shfl_xor_sync(0xffffffffu, c1, m);
        c2 += __shfl_xor_sync(0xffffffffu, c2, m);
        c3 += __shfl_xor_sync(0xffffffffu, c3, m);
    }
    if ((threadIdx.x & 31) == 0) {
        atomicAdd(&ssum[0], c0);
        atomicAdd(&ssum[1], c1);
        atomicAdd(&ssum[2], c2);
        atomicAdd(&ssum[3], c3);
    }
    __syncthreads();
    if (threadIdx.x < HEADS) atomicAdd(&g_sum[threadIdx.x], ssum[threadIdx.x]);
}

// ---------------- 5: weighted scatter-aggregate (warp per edge) ------------
__global__ void __launch_bounds__(256) agg_kernel(const void* __restrict__ ei_raw) {
    int wid = threadIdx.x >> 5;
    int lane = threadIdx.x & 31;
    int e = blockIdx.x * 8 + wid;
    int idx64 = g_idx64;

    int s, t;
    load_edge(ei_raw, e, idx64, s, t);

    int h = lane >> 3;
    float coef = g_logit[(size_t)e * HEADS + h] * (1.0f / g_sum[h]);

    const float4* v = (const float4*)(g_V + (size_t)s * QKVC);
    float4 v0 = v[lane * 2], v1 = v[lane * 2 + 1];

    float* dst = g_agg + (size_t)t * QKVC + lane * 8;
    red_add_v4(dst,     coef * v0.x, coef * v0.y, coef * v0.z, coef * v0.w);
    red_add_v4(dst + 4, coef * v1.x, coef * v1.y, coef * v1.z, coef * v1.w);
}

// ---------------- 6: output GEMM (+bias), 64x64x16 -------------------------
__global__ void __launch_bounds__(256) out_gemm_kernel(
    const float* __restrict__ B, const float* __restrict__ bias,
    float* __restrict__ C)
{
    const int BM = 64, BK = 16;
    const int M = N_NODES, K = QKVC, NB = OUTC;
    __shared__ float As[BM][BK + 1];
    __shared__ float Bs[BK][68];

    int tid = threadIdx.x;
    int row0 = blockIdx.x * BM;
    int tx = tid & 15, ty = tid >> 4;

    float acc[4][4];
#pragma unroll
    for (int i = 0; i < 4; i++)
#pragma unroll
        for (int j = 0; j < 4; j++) acc[i][j] = 0.f;

    for (int k0 = 0; k0 < K; k0 += BK) {
        {
            int r = tid >> 2;
            int c4 = (tid & 3) * 4;
            int gr = row0 + r;
            float4 v = make_float4(0.f, 0.f, 0.f, 0.f);
            if (gr < M) v = *(const float4*)&g_agg[(size_t)gr * K + k0 + c4];
            As[r][c4 + 0] = v.x; As[r][c4 + 1] = v.y;
            As[r][c4 + 2] = v.z; As[r][c4 + 3] = v.w;
        }
        {
            int r = tid >> 4;
            int c4 = (tid & 15) * 4;
            float4 v = *(const float4*)&B[(size_t)(k0 + r) * NB + c4];
            Bs[r][c4 + 0] = v.x; Bs[r][c4 + 1] = v.y;
            Bs[r][c4 + 2] = v.z; Bs[r][c4 + 3] = v.w;
        }
        __syncthreads();
#pragma unroll
        for (int k = 0; k < BK; k++) {
            float ar[4], br[4];
#pragma unroll
            for (int i = 0; i < 4; i++) ar[i] = As[ty * 4 + i][k];
#pragma unroll
            for (int j = 0; j < 4; j++) br[j] = Bs[k][tx * 4 + j];
#pragma unroll
            for (int i = 0; i < 4; i++)
#pragma unroll
                for (int j = 0; j < 4; j++) acc[i][j] += ar[i] * br[j];
        }
        __syncthreads();
    }

#pragma unroll
    for (int i = 0; i < 4; i++) {
        int r = row0 + ty * 4 + i;
        if (r >= M) continue;
#pragma unroll
        for (int j = 0; j < 4; j++) {
            int c = tx * 4 + j;
            C[(size_t)r * NB + c] = acc[i][j] + bias[c];
        }
    }
}

// ---------------- launch ----------------------------------------------------
extern "C" void kernel_launch(void* const* d_in, const int* in_sizes, int n_in,
                              void* d_out, int out_size) {
    const float* x    = (const float*)d_in[0];
    const void*  ei   = d_in[1];
    const float* ew   = (const float*)d_in[2];
    const float* Wq   = (const float*)d_in[3];
    const float* Wk   = (const float*)d_in[4];
    const float* Wv   = (const float*)d_in[5];
    const float* We   = (const float*)d_in[6];
    const float* Wout = (const float*)d_in[7];
    const float* bout = (const float*)d_in[8];
    float* out = (float*)d_out;

    static bool attr_set = false;
    if (!attr_set) {
        cudaFuncSetAttribute(qkv_wmma_kernel,
                             cudaFuncAttributeMaxDynamicSharedMemorySize, SM_QKV);
        attr_set = true;
    }

    detect_idx_kernel<<<1, 32>>>((const int*)ei);

    int zb = (int)(((size_t)N_PAD * QKVC) / 1024);
    zero_kernel<<<zb, 256>>>();

    prep_x_kernel<<<(N_PAD * 16 + 255) / 256, 256>>>(x);
    prep_w_kernel<<<48, 256>>>(Wq, Wk, Wv);

    dim3 qgrid(M_TILES, 2);
    qkv_wmma_kernel<<<qgrid, 256, SM_QKV>>>();

    edge_logits_kernel<<<LOGIT_BLOCKS, 256>>>(ei, ew, We);
    reduce_max_kernel<<<HEADS, 256>>>();
    coef_kernel<<<(N_EDGES + 255) / 256, 256>>>();
    agg_kernel<<<LOGIT_BLOCKS, 256>>>(ei);
    out_gemm_kernel<<<N_PAD / 64, 256>>>(Wout, bout, out);
}